// round 1
// baseline (speedup 1.0000x reference)
#include <cuda_runtime.h>

#define N_NODES 50000
#define N_EDGES 800000

// ---------------- device scratch (static: no allocation allowed) ----------------
__device__ int   g_is64;
__device__ int   g_deg[N_NODES];
__device__ int   g_offs[N_NODES + 1];
__device__ int   g_cursor[N_NODES];
__device__ int   g_esrc[N_EDGES];
__device__ float g_agg1[(size_t)N_NODES * 128];
__device__ float g_h1[(size_t)N_NODES * 128];
__device__ float g_p2[(size_t)N_NODES * 64];

// ---------------- dtype detection: int64 vs int32 edge indices ----------------
// If indices are int64 (little-endian), every odd 32-bit word is the high half = 0
// (values < 50000). If int32, odd words are random indices; P(1024 all zero) ~ 0.
__global__ void k_detect(const unsigned int* __restrict__ src) {
    __shared__ int any;
    if (threadIdx.x == 0) any = 0;
    __syncthreads();
    unsigned v = src[2 * threadIdx.x + 1];
    if (v != 0u) any = 1;   // benign race
    __syncthreads();
    if (threadIdx.x == 0) g_is64 = (any == 0) ? 1 : 0;
}

__device__ __forceinline__ int load_idx(const void* p, int i, int is64) {
    return is64 ? (int)(((const long long*)p)[i]) : ((const int*)p)[i];
}

// ---------------- CSC build ----------------
__global__ void k_zero_deg(int n) {
    int i = blockIdx.x * blockDim.x + threadIdx.x;
    if (i < n) g_deg[i] = 0;
}

__global__ void k_hist(const void* __restrict__ dst, int E) {
    int e = blockIdx.x * blockDim.x + threadIdx.x;
    if (e >= E) return;
    int is64 = g_is64;
    int d = load_idx(dst, e, is64);
    atomicAdd(&g_deg[d], 1);
}

// single-block chunked exclusive scan over g_deg -> g_offs, g_cursor
__global__ void k_scan(int n) {
    __shared__ int warp_sums[32];
    __shared__ int s_carry;
    int tid = threadIdx.x, lane = tid & 31, wid = tid >> 5;
    if (tid == 0) s_carry = 0;
    __syncthreads();
    for (int base = 0; base < n; base += 1024) {
        int i = base + tid;
        int v = (i < n) ? g_deg[i] : 0;
        int x = v;
        #pragma unroll
        for (int o = 1; o < 32; o <<= 1) {
            int y = __shfl_up_sync(0xFFFFFFFFu, x, o);
            if (lane >= o) x += y;
        }
        __syncthreads();                 // protect warp_sums reuse
        if (lane == 31) warp_sums[wid] = x;
        __syncthreads();
        if (wid == 0) {
            int w = warp_sums[lane];
            #pragma unroll
            for (int o = 1; o < 32; o <<= 1) {
                int y = __shfl_up_sync(0xFFFFFFFFu, w, o);
                if (lane >= o) w += y;
            }
            warp_sums[lane] = w;
        }
        __syncthreads();
        int excl = s_carry + (wid ? warp_sums[wid - 1] : 0) + x - v;
        if (i < n) { g_offs[i] = excl; g_cursor[i] = excl; }
        __syncthreads();                 // all reads of s_carry/warp_sums done
        if (tid == 0) s_carry += warp_sums[31];
    }
    if (tid == 0) g_offs[n] = s_carry;
}

__global__ void k_scatter(const void* __restrict__ src, const void* __restrict__ dst, int E) {
    int e = blockIdx.x * blockDim.x + threadIdx.x;
    if (e >= E) return;
    int is64 = g_is64;
    int s = load_idx(src, e, is64);
    int d = load_idx(dst, e, is64);
    int p = atomicAdd(&g_cursor[d], 1);
    g_esrc[p] = s;
}

// ---------------- aggregation layer 1: agg1[v] = mean_{e: dst=v} feat[src[e]] ----------------
// one warp per node, lane covers 4 floats (128 cols / 32 lanes)
__global__ void k_agg1(const float4* __restrict__ feat, int M) {
    int warp = (blockIdx.x * blockDim.x + threadIdx.x) >> 5;
    int lane = threadIdx.x & 31;
    if (warp >= M) return;
    int beg = g_offs[warp], end = g_offs[warp + 1];
    float4 acc = make_float4(0.f, 0.f, 0.f, 0.f);
    int e = beg;
    for (; e + 1 < end; e += 2) {
        int s0 = __ldg(&g_esrc[e]);
        int s1 = __ldg(&g_esrc[e + 1]);
        float4 t0 = __ldg(&feat[(size_t)s0 * 32 + lane]);
        float4 t1 = __ldg(&feat[(size_t)s1 * 32 + lane]);
        acc.x += t0.x; acc.y += t0.y; acc.z += t0.z; acc.w += t0.w;
        acc.x += t1.x; acc.y += t1.y; acc.z += t1.z; acc.w += t1.w;
    }
    if (e < end) {
        int s0 = __ldg(&g_esrc[e]);
        float4 t0 = __ldg(&feat[(size_t)s0 * 32 + lane]);
        acc.x += t0.x; acc.y += t0.y; acc.z += t0.z; acc.w += t0.w;
    }
    int deg = end - beg;
    float inv = 1.0f / (float)(deg > 0 ? deg : 1);
    acc.x *= inv; acc.y *= inv; acc.z *= inv; acc.w *= inv;
    ((float4*)g_agg1)[(size_t)warp * 32 + lane] = acc;
}

// ---------------- GEMM layer 1: h1 = relu([feat|agg1] @ [Ws1;Wn1] + b1) ----------------
// BM=64, BN=128, BK=32, 256 threads, each thread 8x4 outputs
__global__ __launch_bounds__(256) void k_gemm1(
    const float* __restrict__ A0, const float* __restrict__ W0,
    const float* __restrict__ W1, const float* __restrict__ bias, int M)
{
    __shared__ float As[32][64];
    __shared__ float Ws[32][128];
    int tid = threadIdx.x;
    int row0 = blockIdx.x * 64;
    int tcol = (tid & 31) * 4;
    int trow = (tid >> 5) * 8;
    int a_r = tid >> 3;      // 0..31
    int a_c = tid & 7;       // 0..7 (float4 col within 32-wide k tile)
    float acc[8][4];
    #pragma unroll
    for (int i = 0; i < 8; i++)
        #pragma unroll
        for (int j = 0; j < 4; j++) acc[i][j] = 0.f;

    for (int kt = 0; kt < 8; kt++) {
        const float* Asrc = (kt < 4) ? A0 : g_agg1;
        const float* Wsrc = (kt < 4) ? W0 : W1;
        int kb = (kt & 3) * 32;
        // load A tile (transposed into shared)
        #pragma unroll
        for (int h = 0; h < 2; h++) {
            int r = a_r + h * 32;
            int grow = row0 + r;
            float4 v = make_float4(0.f, 0.f, 0.f, 0.f);
            if (grow < M) v = *(const float4*)&Asrc[(size_t)grow * 128 + kb + a_c * 4];
            As[a_c * 4 + 0][r] = v.x;
            As[a_c * 4 + 1][r] = v.y;
            As[a_c * 4 + 2][r] = v.z;
            As[a_c * 4 + 3][r] = v.w;
        }
        // load W tile
        #pragma unroll
        for (int h = 0; h < 4; h++) {
            int c4 = (tid & 7) + 8 * h;
            float4 wv = *(const float4*)&Wsrc[(size_t)(kb + (tid >> 3)) * 128 + c4 * 4];
            *(float4*)&Ws[tid >> 3][c4 * 4] = wv;
        }
        __syncthreads();
        #pragma unroll
        for (int kk = 0; kk < 32; kk++) {
            float4 b = *(float4*)&Ws[kk][tcol];
            float4 a0 = *(float4*)&As[kk][trow];
            float4 a1 = *(float4*)&As[kk][trow + 4];
            float a[8] = {a0.x, a0.y, a0.z, a0.w, a1.x, a1.y, a1.z, a1.w};
            #pragma unroll
            for (int i = 0; i < 8; i++) {
                acc[i][0] += a[i] * b.x;
                acc[i][1] += a[i] * b.y;
                acc[i][2] += a[i] * b.z;
                acc[i][3] += a[i] * b.w;
            }
        }
        __syncthreads();
    }
    float4 bv = *(const float4*)&bias[tcol];
    #pragma unroll
    for (int i = 0; i < 8; i++) {
        int grow = row0 + trow + i;
        if (grow < M) {
            float4 o;
            o.x = fmaxf(acc[i][0] + bv.x, 0.f);
            o.y = fmaxf(acc[i][1] + bv.y, 0.f);
            o.z = fmaxf(acc[i][2] + bv.z, 0.f);
            o.w = fmaxf(acc[i][3] + bv.w, 0.f);
            *(float4*)&g_h1[(size_t)grow * 128 + tcol] = o;
        }
    }
}

// ---------------- GEMM layer 2: [d_out | p2] = h1 @ [Ws2 | Wn2] (+b2 on self half) ----------------
__global__ __launch_bounds__(256) void k_gemm2(
    const float* __restrict__ Wself, const float* __restrict__ Wneigh,
    const float* __restrict__ bias, float* __restrict__ out, int M)
{
    __shared__ float As[32][64];
    __shared__ float Ws[32][128];
    int tid = threadIdx.x;
    int row0 = blockIdx.x * 64;
    int tcol = (tid & 31) * 4;
    int trow = (tid >> 5) * 8;
    int a_r = tid >> 3;
    int a_c = tid & 7;
    float acc[8][4];
    #pragma unroll
    for (int i = 0; i < 8; i++)
        #pragma unroll
        for (int j = 0; j < 4; j++) acc[i][j] = 0.f;

    for (int kt = 0; kt < 4; kt++) {
        int kb = kt * 32;
        #pragma unroll
        for (int h = 0; h < 2; h++) {
            int r = a_r + h * 32;
            int grow = row0 + r;
            float4 v = make_float4(0.f, 0.f, 0.f, 0.f);
            if (grow < M) v = *(const float4*)&g_h1[(size_t)grow * 128 + kb + a_c * 4];
            As[a_c * 4 + 0][r] = v.x;
            As[a_c * 4 + 1][r] = v.y;
            As[a_c * 4 + 2][r] = v.z;
            As[a_c * 4 + 3][r] = v.w;
        }
        #pragma unroll
        for (int h = 0; h < 4; h++) {
            int c4 = (tid & 7) + 8 * h;   // 0..31 -> cols c4*4
            int w_r = tid >> 3;           // 0..31
            float4 wv;
            if (c4 < 16)
                wv = *(const float4*)&Wself[(size_t)(kb + w_r) * 64 + c4 * 4];
            else
                wv = *(const float4*)&Wneigh[(size_t)(kb + w_r) * 64 + (c4 - 16) * 4];
            *(float4*)&Ws[w_r][c4 * 4] = wv;
        }
        __syncthreads();
        #pragma unroll
        for (int kk = 0; kk < 32; kk++) {
            float4 b = *(float4*)&Ws[kk][tcol];
            float4 a0 = *(float4*)&As[kk][trow];
            float4 a1 = *(float4*)&As[kk][trow + 4];
            float a[8] = {a0.x, a0.y, a0.z, a0.w, a1.x, a1.y, a1.z, a1.w};
            #pragma unroll
            for (int i = 0; i < 8; i++) {
                acc[i][0] += a[i] * b.x;
                acc[i][1] += a[i] * b.y;
                acc[i][2] += a[i] * b.z;
                acc[i][3] += a[i] * b.w;
            }
        }
        __syncthreads();
    }
    bool self_half = (tcol < 64);
    float4 bv = make_float4(0.f, 0.f, 0.f, 0.f);
    if (self_half) bv = *(const float4*)&bias[tcol];
    #pragma unroll
    for (int i = 0; i < 8; i++) {
        int grow = row0 + trow + i;
        if (grow < M) {
            float4 o;
            o.x = acc[i][0] + bv.x;
            o.y = acc[i][1] + bv.y;
            o.z = acc[i][2] + bv.z;
            o.w = acc[i][3] + bv.w;
            if (self_half)
                *(float4*)&out[(size_t)grow * 64 + tcol] = o;
            else
                *(float4*)&g_p2[(size_t)grow * 64 + (tcol - 64)] = o;
        }
    }
}

// ---------------- aggregation layer 2: out[v] += mean_{e: dst=v} p2[src[e]] ----------------
// one warp per node, lane covers 2 floats (64 cols / 32 lanes)
__global__ void k_agg2(float2* __restrict__ out, int M) {
    int warp = (blockIdx.x * blockDim.x + threadIdx.x) >> 5;
    int lane = threadIdx.x & 31;
    if (warp >= M) return;
    int beg = g_offs[warp], end = g_offs[warp + 1];
    float2 acc = make_float2(0.f, 0.f);
    const float2* p2 = (const float2*)g_p2;
    int e = beg;
    for (; e + 1 < end; e += 2) {
        int s0 = __ldg(&g_esrc[e]);
        int s1 = __ldg(&g_esrc[e + 1]);
        float2 t0 = __ldg(&p2[(size_t)s0 * 32 + lane]);
        float2 t1 = __ldg(&p2[(size_t)s1 * 32 + lane]);
        acc.x += t0.x + t1.x;
        acc.y += t0.y + t1.y;
    }
    if (e < end) {
        int s0 = __ldg(&g_esrc[e]);
        float2 t0 = __ldg(&p2[(size_t)s0 * 32 + lane]);
        acc.x += t0.x; acc.y += t0.y;
    }
    int deg = end - beg;
    float inv = 1.0f / (float)(deg > 0 ? deg : 1);
    float2 o = out[(size_t)warp * 32 + lane];
    o.x += acc.x * inv;
    o.y += acc.y * inv;
    out[(size_t)warp * 32 + lane] = o;
}

// ---------------- launch ----------------
extern "C" void kernel_launch(void* const* d_in, const int* in_sizes, int n_in,
                              void* d_out, int out_size) {
    const float* feat = (const float*)d_in[0];
    const void*  src  = d_in[1];
    const void*  dst  = d_in[2];
    const float* Ws1  = (const float*)d_in[3];
    const float* Wn1  = (const float*)d_in[4];
    const float* b1   = (const float*)d_in[5];
    const float* Ws2  = (const float*)d_in[6];
    const float* Wn2  = (const float*)d_in[7];
    const float* b2   = (const float*)d_in[8];

    int M = in_sizes[0] / 128;   // 50000
    int E = in_sizes[1];         // 800000

    k_detect<<<1, 1024>>>((const unsigned int*)src);
    k_zero_deg<<<(M + 255) / 256, 256>>>(M);
    k_hist<<<(E + 255) / 256, 256>>>(dst, E);
    k_scan<<<1, 1024>>>(M);
    k_scatter<<<(E + 255) / 256, 256>>>(src, dst, E);

    int agg_blocks = (M + 7) / 8;           // 8 warps/block, warp per node
    k_agg1<<<agg_blocks, 256>>>((const float4*)feat, M);

    int gemm_blocks = (M + 63) / 64;
    k_gemm1<<<gemm_blocks, 256>>>(feat, Ws1, Wn1, b1, M);
    k_gemm2<<<gemm_blocks, 256>>>(Ws2, Wn2, b2, (float*)d_out, M);

    k_agg2<<<agg_blocks, 256>>>((float2*)d_out, M);
}

// round 3
// speedup vs baseline: 1.7803x; 1.7803x over previous
#include <cuda_runtime.h>

#define N_NODES 50000
#define N_EDGES 800000

// ---------------- device scratch (static: no allocation allowed) ----------------
__device__ int   g_is64;
__device__ int   g_deg[N_NODES];
__device__ int   g_offs[N_NODES + 1];
__device__ int   g_cursor[N_NODES];
__device__ int   g_esrc[N_EDGES];
__device__ int   g_bsum[256];
__device__ int   g_boff[256];
__device__ float g_agg1[(size_t)N_NODES * 128];
__device__ float g_h1[(size_t)N_NODES * 128];
__device__ float g_p2[(size_t)N_NODES * 64];

// ---------------- dtype detection: int64 vs int32 edge indices ----------------
__global__ void k_detect(const unsigned int* __restrict__ src) {
    __shared__ int any;
    if (threadIdx.x == 0) any = 0;
    __syncthreads();
    unsigned v = src[2 * threadIdx.x + 1];
    if (v != 0u) any = 1;   // benign race
    __syncthreads();
    if (threadIdx.x == 0) g_is64 = (any == 0) ? 1 : 0;
}

__device__ __forceinline__ int load_idx(const void* p, int i, int is64) {
    return is64 ? (int)(((const long long*)p)[i]) : ((const int*)p)[i];
}

// ---------------- CSC build ----------------
__global__ void k_zero_deg(int n) {
    int i = blockIdx.x * blockDim.x + threadIdx.x;
    if (i < n) g_deg[i] = 0;
}

__global__ void k_hist(const void* __restrict__ dst, int E) {
    int e = blockIdx.x * blockDim.x + threadIdx.x;
    if (e >= E) return;
    int is64 = g_is64;
    int d = load_idx(dst, e, is64);
    atomicAdd(&g_deg[d], 1);
}

// --- multi-block exclusive scan: phase 1, per-block sums ---
__global__ void k_bsum(int n) {
    __shared__ int wsum[8];
    int b = blockIdx.x, tid = threadIdx.x;
    int i = b * 256 + tid;
    int v = (i < n) ? g_deg[i] : 0;
    #pragma unroll
    for (int o = 16; o > 0; o >>= 1) v += __shfl_down_sync(0xFFFFFFFFu, v, o);
    if ((tid & 31) == 0) wsum[tid >> 5] = v;
    __syncthreads();
    if (tid == 0) {
        int s = 0;
        #pragma unroll
        for (int w = 0; w < 8; w++) s += wsum[w];
        g_bsum[b] = s;
    }
}

// --- phase 2: scan of block sums (single tiny block) ---
__global__ void k_bscan(int B) {
    __shared__ int wsum[8];
    int tid = threadIdx.x, lane = tid & 31, wid = tid >> 5;
    int v = (tid < B) ? g_bsum[tid] : 0;
    int x = v;
    #pragma unroll
    for (int o = 1; o < 32; o <<= 1) {
        int y = __shfl_up_sync(0xFFFFFFFFu, x, o);
        if (lane >= o) x += y;
    }
    if (lane == 31) wsum[wid] = x;
    __syncthreads();
    int carry = 0;
    #pragma unroll
    for (int w = 0; w < 8; w++) {
        if (w < wid) carry += wsum[w];
    }
    if (tid < B) g_boff[tid] = carry + x - v;   // exclusive
}

// --- phase 3: per-block scan + apply offset ---
__global__ void k_bapply(int n) {
    __shared__ int wsum[8];
    int b = blockIdx.x, tid = threadIdx.x, lane = tid & 31, wid = tid >> 5;
    int i = b * 256 + tid;
    int v = (i < n) ? g_deg[i] : 0;
    int x = v;
    #pragma unroll
    for (int o = 1; o < 32; o <<= 1) {
        int y = __shfl_up_sync(0xFFFFFFFFu, x, o);
        if (lane >= o) x += y;
    }
    if (lane == 31) wsum[wid] = x;
    __syncthreads();
    int carry = g_boff[b];
    #pragma unroll
    for (int w = 0; w < 8; w++) {
        if (w < wid) carry += wsum[w];
    }
    int excl = carry + x - v;
    if (i < n) { g_offs[i] = excl; g_cursor[i] = excl; }
    if (i == n - 1) g_offs[n] = excl + v;
}

__global__ void k_scatter(const void* __restrict__ src, const void* __restrict__ dst, int E) {
    int e = blockIdx.x * blockDim.x + threadIdx.x;
    if (e >= E) return;
    int is64 = g_is64;
    int s = load_idx(src, e, is64);
    int d = load_idx(dst, e, is64);
    int p = atomicAdd(&g_cursor[d], 1);
    g_esrc[p] = s;
}

// ---------------- aggregation layer 1 (pull-mode, warp per node) ----------------
__global__ void k_agg1(const float4* __restrict__ feat, int M) {
    int warp = (blockIdx.x * blockDim.x + threadIdx.x) >> 5;
    int lane = threadIdx.x & 31;
    if (warp >= M) return;
    int beg = g_offs[warp], end = g_offs[warp + 1];
    float4 acc = make_float4(0.f, 0.f, 0.f, 0.f);
    int e = beg;
    for (; e + 1 < end; e += 2) {
        int s0 = __ldg(&g_esrc[e]);
        int s1 = __ldg(&g_esrc[e + 1]);
        float4 t0 = __ldg(&feat[(size_t)s0 * 32 + lane]);
        float4 t1 = __ldg(&feat[(size_t)s1 * 32 + lane]);
        acc.x += t0.x; acc.y += t0.y; acc.z += t0.z; acc.w += t0.w;
        acc.x += t1.x; acc.y += t1.y; acc.z += t1.z; acc.w += t1.w;
    }
    if (e < end) {
        int s0 = __ldg(&g_esrc[e]);
        float4 t0 = __ldg(&feat[(size_t)s0 * 32 + lane]);
        acc.x += t0.x; acc.y += t0.y; acc.z += t0.z; acc.w += t0.w;
    }
    int deg = end - beg;
    float inv = 1.0f / (float)(deg > 0 ? deg : 1);
    acc.x *= inv; acc.y *= inv; acc.z *= inv; acc.w *= inv;
    ((float4*)g_agg1)[(size_t)warp * 32 + lane] = acc;
}

// ---------------- tf32 tensor-core GEMMs ----------------
// Block 128x128, 8 warps (4m x 2n), each warp 32x64 via mma.m16n8k8.tf32.
#define LDA_S 36
#define LDB_S 136

__device__ __forceinline__ unsigned f2tf32(float f) {
    unsigned r;
    asm("cvt.rna.tf32.f32 %0, %1;" : "=r"(r) : "f"(f));
    return r;
}

__device__ __forceinline__ void mma_tf32(float* c, const unsigned* a, const unsigned* b) {
    asm("mma.sync.aligned.m16n8k8.row.col.f32.tf32.tf32.f32 "
        "{%0,%1,%2,%3}, {%4,%5,%6,%7}, {%8,%9}, {%0,%1,%2,%3};"
        : "+f"(c[0]), "+f"(c[1]), "+f"(c[2]), "+f"(c[3])
        : "r"(a[0]), "r"(a[1]), "r"(a[2]), "r"(a[3]), "r"(b[0]), "r"(b[1]));
}

// GEMM1: h1 = relu([feat | agg1] @ [Ws1 ; Wn1] + b1)   M x 128, K=256
__global__ __launch_bounds__(256) void k_gemm1(
    const float* __restrict__ A0, const float* __restrict__ W0,
    const float* __restrict__ W1, const float* __restrict__ bias, int M)
{
    __shared__ unsigned As[128 * LDA_S];
    __shared__ unsigned Bs[32 * LDB_S];
    int tid = threadIdx.x, lane = tid & 31, wid = tid >> 5;
    int warp_m = wid >> 1, warp_n = wid & 1;
    int grp = lane >> 2, qk = lane & 3;
    int row0 = blockIdx.x * 128;

    float acc[2][8][4];
    #pragma unroll
    for (int mt = 0; mt < 2; mt++)
        #pragma unroll
        for (int nt = 0; nt < 8; nt++)
            #pragma unroll
            for (int j = 0; j < 4; j++) acc[mt][nt][j] = 0.f;

    for (int kt = 0; kt < 8; kt++) {
        const float* Asrc = (kt < 4) ? A0 : g_agg1;
        const float* Wsrc = (kt < 4) ? W0 : W1;
        int kb = (kt & 3) * 32;
        // A tile: 128 rows x 32 k (8 float4 per row), 1024 float4 / 256 thr
        #pragma unroll
        for (int i = 0; i < 4; i++) {
            int idx = tid + i * 256;
            int r = idx >> 3, c4 = idx & 7;
            int grow = row0 + r;
            float4 v = make_float4(0.f, 0.f, 0.f, 0.f);
            if (grow < M) v = *(const float4*)&Asrc[(size_t)grow * 128 + kb + c4 * 4];
            *(uint4*)&As[r * LDA_S + c4 * 4] =
                make_uint4(f2tf32(v.x), f2tf32(v.y), f2tf32(v.z), f2tf32(v.w));
        }
        // B tile: 32 k-rows x 128 n
        #pragma unroll
        for (int i = 0; i < 4; i++) {
            int idx = tid + i * 256;
            int r = idx >> 5, c4 = idx & 31;
            float4 w = *(const float4*)&Wsrc[(size_t)(kb + r) * 128 + c4 * 4];
            *(uint4*)&Bs[r * LDB_S + c4 * 4] =
                make_uint4(f2tf32(w.x), f2tf32(w.y), f2tf32(w.z), f2tf32(w.w));
        }
        __syncthreads();
        #pragma unroll
        for (int ks = 0; ks < 4; ks++) {
            unsigned a[2][4], b[8][2];
            #pragma unroll
            for (int mt = 0; mt < 2; mt++) {
                int rb = warp_m * 32 + mt * 16 + grp;
                // PTX m16n8k8 A fragment: a0=(r,k) a1=(r+8,k) a2=(r,k+4) a3=(r+8,k+4)
                a[mt][0] = As[rb * LDA_S + ks * 8 + qk];
                a[mt][1] = As[(rb + 8) * LDA_S + ks * 8 + qk];
                a[mt][2] = As[rb * LDA_S + ks * 8 + qk + 4];
                a[mt][3] = As[(rb + 8) * LDA_S + ks * 8 + qk + 4];
            }
            #pragma unroll
            for (int nt = 0; nt < 8; nt++) {
                int col = warp_n * 64 + nt * 8 + grp;
                b[nt][0] = Bs[(ks * 8 + qk) * LDB_S + col];
                b[nt][1] = Bs[(ks * 8 + qk + 4) * LDB_S + col];
            }
            #pragma unroll
            for (int mt = 0; mt < 2; mt++)
                #pragma unroll
                for (int nt = 0; nt < 8; nt++)
                    mma_tf32(acc[mt][nt], a[mt], b[nt]);
        }
        __syncthreads();
    }
    // epilogue: bias + relu
    #pragma unroll
    for (int mt = 0; mt < 2; mt++) {
        #pragma unroll
        for (int nt = 0; nt < 8; nt++) {
            int c = warp_n * 64 + nt * 8 + 2 * qk;
            float bx = bias[c], by = bias[c + 1];
            int r = row0 + warp_m * 32 + mt * 16 + grp;
            if (r < M) {
                float2 o;
                o.x = fmaxf(acc[mt][nt][0] + bx, 0.f);
                o.y = fmaxf(acc[mt][nt][1] + by, 0.f);
                *(float2*)&g_h1[(size_t)r * 128 + c] = o;
            }
            if (r + 8 < M) {
                float2 o;
                o.x = fmaxf(acc[mt][nt][2] + bx, 0.f);
                o.y = fmaxf(acc[mt][nt][3] + by, 0.f);
                *(float2*)&g_h1[(size_t)(r + 8) * 128 + c] = o;
            }
        }
    }
}

// GEMM2: [d_out | p2] = h1 @ [Ws2 | Wn2] (+b2 on self half)   M x 128, K=128
__global__ __launch_bounds__(256) void k_gemm2(
    const float* __restrict__ Wself, const float* __restrict__ Wneigh,
    const float* __restrict__ bias, float* __restrict__ out, int M)
{
    __shared__ unsigned As[128 * LDA_S];
    __shared__ unsigned Bs[32 * LDB_S];
    int tid = threadIdx.x, lane = tid & 31, wid = tid >> 5;
    int warp_m = wid >> 1, warp_n = wid & 1;
    int grp = lane >> 2, qk = lane & 3;
    int row0 = blockIdx.x * 128;

    float acc[2][8][4];
    #pragma unroll
    for (int mt = 0; mt < 2; mt++)
        #pragma unroll
        for (int nt = 0; nt < 8; nt++)
            #pragma unroll
            for (int j = 0; j < 4; j++) acc[mt][nt][j] = 0.f;

    for (int kt = 0; kt < 4; kt++) {
        int kb = kt * 32;
        #pragma unroll
        for (int i = 0; i < 4; i++) {
            int idx = tid + i * 256;
            int r = idx >> 3, c4 = idx & 7;
            int grow = row0 + r;
            float4 v = make_float4(0.f, 0.f, 0.f, 0.f);
            if (grow < M) v = *(const float4*)&g_h1[(size_t)grow * 128 + kb + c4 * 4];
            *(uint4*)&As[r * LDA_S + c4 * 4] =
                make_uint4(f2tf32(v.x), f2tf32(v.y), f2tf32(v.z), f2tf32(v.w));
        }
        #pragma unroll
        for (int i = 0; i < 4; i++) {
            int idx = tid + i * 256;
            int r = idx >> 5, c4 = idx & 31;
            float4 w;
            if (c4 < 16)
                w = *(const float4*)&Wself[(size_t)(kb + r) * 64 + c4 * 4];
            else
                w = *(const float4*)&Wneigh[(size_t)(kb + r) * 64 + (c4 - 16) * 4];
            *(uint4*)&Bs[r * LDB_S + c4 * 4] =
                make_uint4(f2tf32(w.x), f2tf32(w.y), f2tf32(w.z), f2tf32(w.w));
        }
        __syncthreads();
        #pragma unroll
        for (int ks = 0; ks < 4; ks++) {
            unsigned a[2][4], b[8][2];
            #pragma unroll
            for (int mt = 0; mt < 2; mt++) {
                int rb = warp_m * 32 + mt * 16 + grp;
                a[mt][0] = As[rb * LDA_S + ks * 8 + qk];
                a[mt][1] = As[(rb + 8) * LDA_S + ks * 8 + qk];
                a[mt][2] = As[rb * LDA_S + ks * 8 + qk + 4];
                a[mt][3] = As[(rb + 8) * LDA_S + ks * 8 + qk + 4];
            }
            #pragma unroll
            for (int nt = 0; nt < 8; nt++) {
                int col = warp_n * 64 + nt * 8 + grp;
                b[nt][0] = Bs[(ks * 8 + qk) * LDB_S + col];
                b[nt][1] = Bs[(ks * 8 + qk + 4) * LDB_S + col];
            }
            #pragma unroll
            for (int mt = 0; mt < 2; mt++)
                #pragma unroll
                for (int nt = 0; nt < 8; nt++)
                    mma_tf32(acc[mt][nt], a[mt], b[nt]);
        }
        __syncthreads();
    }
    // epilogue: cols<64 -> out (+bias), cols>=64 -> g_p2
    #pragma unroll
    for (int mt = 0; mt < 2; mt++) {
        #pragma unroll
        for (int nt = 0; nt < 8; nt++) {
            int c = warp_n * 64 + nt * 8 + 2 * qk;
            bool self_half = (c < 64);
            float bx = 0.f, by = 0.f;
            if (self_half) { bx = bias[c]; by = bias[c + 1]; }
            int r = row0 + warp_m * 32 + mt * 16 + grp;
            #pragma unroll
            for (int h = 0; h < 2; h++) {
                int rr = r + h * 8;
                if (rr < M) {
                    float2 o;
                    o.x = acc[mt][nt][2 * h + 0] + bx;
                    o.y = acc[mt][nt][2 * h + 1] + by;
                    if (self_half)
                        *(float2*)&out[(size_t)rr * 64 + c] = o;
                    else
                        *(float2*)&g_p2[(size_t)rr * 64 + (c - 64)] = o;
                }
            }
        }
    }
}

// ---------------- aggregation layer 2 ----------------
__global__ void k_agg2(float2* __restrict__ out, int M) {
    int warp = (blockIdx.x * blockDim.x + threadIdx.x) >> 5;
    int lane = threadIdx.x & 31;
    if (warp >= M) return;
    int beg = g_offs[warp], end = g_offs[warp + 1];
    float2 acc = make_float2(0.f, 0.f);
    const float2* p2 = (const float2*)g_p2;
    int e = beg;
    for (; e + 1 < end; e += 2) {
        int s0 = __ldg(&g_esrc[e]);
        int s1 = __ldg(&g_esrc[e + 1]);
        float2 t0 = __ldg(&p2[(size_t)s0 * 32 + lane]);
        float2 t1 = __ldg(&p2[(size_t)s1 * 32 + lane]);
        acc.x += t0.x + t1.x;
        acc.y += t0.y + t1.y;
    }
    if (e < end) {
        int s0 = __ldg(&g_esrc[e]);
        float2 t0 = __ldg(&p2[(size_t)s0 * 32 + lane]);
        acc.x += t0.x; acc.y += t0.y;
    }
    int deg = end - beg;
    float inv = 1.0f / (float)(deg > 0 ? deg : 1);
    float2 o = out[(size_t)warp * 32 + lane];
    o.x += acc.x * inv;
    o.y += acc.y * inv;
    out[(size_t)warp * 32 + lane] = o;
}

// ---------------- launch ----------------
extern "C" void kernel_launch(void* const* d_in, const int* in_sizes, int n_in,
                              void* d_out, int out_size) {
    const float* feat = (const float*)d_in[0];
    const void*  src  = d_in[1];
    const void*  dst  = d_in[2];
    const float* Ws1  = (const float*)d_in[3];
    const float* Wn1  = (const float*)d_in[4];
    const float* b1   = (const float*)d_in[5];
    const float* Ws2  = (const float*)d_in[6];
    const float* Wn2  = (const float*)d_in[7];
    const float* b2   = (const float*)d_in[8];

    int M = in_sizes[0] / 128;   // 50000
    int E = in_sizes[1];         // 800000
    int B = (M + 255) / 256;     // 196 scan blocks

    k_detect<<<1, 1024>>>((const unsigned int*)src);
    k_zero_deg<<<(M + 255) / 256, 256>>>(M);
    k_hist<<<(E + 255) / 256, 256>>>(dst, E);
    k_bsum<<<B, 256>>>(M);
    k_bscan<<<1, 256>>>(B);
    k_bapply<<<B, 256>>>(M);
    k_scatter<<<(E + 255) / 256, 256>>>(src, dst, E);

    int agg_blocks = (M + 7) / 8;
    k_agg1<<<agg_blocks, 256>>>((const float4*)feat, M);

    int gemm_blocks = (M + 127) / 128;
    k_gemm1<<<gemm_blocks, 256>>>(feat, Ws1, Wn1, b1, M);
    k_gemm2<<<gemm_blocks, 256>>>(Ws2, Wn2, b2, (float*)d_out, M);

    k_agg2<<<agg_blocks, 256>>>((float2*)d_out, M);
}